// round 4
// baseline (speedup 1.0000x reference)
#include <cuda_runtime.h>

// LinearAttention: B=16, DK=64, N=8192, DV=64, fp32.
//   ktv[b,k,j] = sum_n k[b,n,k] * v[b,n,j]
//   out[b,n,j] = sum_k q[b,k,n] * ktv[b,k,j]
// Inputs (metadata order): q [B,DK,N], k [B,N,DK], v [B,N,DV]. Output [B,N,DV] fp32.

#define BATCH 16
#define DKC   64
#define NSEQ  8192
#define DVC   64
#define S1    64            // phase-1 N-splits
#define CHUNK (NSEQ / S1)   // 128 rows per phase-1 block

// Scratch (device globals; no allocation at runtime).
__device__ float g_part[BATCH * S1 * DKC * DVC];  // 16 MB partial ktv
__device__ float g_ktv [BATCH * DKC * DVC];       // 256 KB reduced ktv

// ---- packed f32x2 helpers (Blackwell FFMA2 via PTX) ----
__device__ __forceinline__ unsigned long long pack2(float x) {
    unsigned long long r;
    asm("mov.b64 %0, {%1, %1};" : "=l"(r) : "f"(x));
    return r;
}
__device__ __forceinline__ void ffma2(unsigned long long& d,
                                      unsigned long long a,
                                      unsigned long long b) {
    asm("fma.rn.f32x2 %0, %1, %2, %0;" : "+l"(d) : "l"(a), "l"(b));
}

// ============================================================================
// Phase 1: partial ktv = k_chunk^T @ v_chunk  (per (batch, split))
// Block: 128 threads. Each thread owns a 4(k-rows) x 8(v-cols) tile of the
// 64x64 output -> 16 FFMA2 per n-step.
// ============================================================================
__global__ __launch_bounds__(128) void phase1_kernel(
    const float* __restrict__ kmat, const float* __restrict__ vmat)
{
    __shared__ float ks[64 * 64];
    __shared__ float vs[64 * 64];

    const int b = blockIdx.y;
    const int s = blockIdx.x;
    const int t = threadIdx.x;

    const int kg = t >> 3;          // 0..15
    const int jg = t & 7;           // 0..7
    const int k0 = kg * 4;
    const int j0 = jg * 8;

    unsigned long long acc[4][4];
#pragma unroll
    for (int i = 0; i < 4; i++)
#pragma unroll
        for (int p = 0; p < 4; p++) acc[i][p] = 0ULL;

    const long base = ((long)b * NSEQ + (long)s * CHUNK) * DKC;

    for (int sub = 0; sub < CHUNK; sub += 64) {
        const float4* kg4 = (const float4*)(kmat + base + (long)sub * DKC);
        const float4* vg4 = (const float4*)(vmat + base + (long)sub * DVC);
        __syncthreads();
#pragma unroll
        for (int i = 0; i < 8; i++) {
            int idx = t + i * 128;                // 1024 float4 per tile
            ((float4*)ks)[idx] = kg4[idx];
            ((float4*)vs)[idx] = vg4[idx];
        }
        __syncthreads();

#pragma unroll 4
        for (int n = 0; n < 64; n++) {
            float4 kk = *(const float4*)(ks + n * 64 + k0);
            ulonglong2 va = *(const ulonglong2*)(vs + n * 64 + j0);
            ulonglong2 vb = *(const ulonglong2*)(vs + n * 64 + j0 + 4);
            unsigned long long kd0 = pack2(kk.x);
            unsigned long long kd1 = pack2(kk.y);
            unsigned long long kd2 = pack2(kk.z);
            unsigned long long kd3 = pack2(kk.w);
            ffma2(acc[0][0], kd0, va.x); ffma2(acc[0][1], kd0, va.y);
            ffma2(acc[0][2], kd0, vb.x); ffma2(acc[0][3], kd0, vb.y);
            ffma2(acc[1][0], kd1, va.x); ffma2(acc[1][1], kd1, va.y);
            ffma2(acc[1][2], kd1, vb.x); ffma2(acc[1][3], kd1, vb.y);
            ffma2(acc[2][0], kd2, va.x); ffma2(acc[2][1], kd2, va.y);
            ffma2(acc[2][2], kd2, vb.x); ffma2(acc[2][3], kd2, vb.y);
            ffma2(acc[3][0], kd3, va.x); ffma2(acc[3][1], kd3, va.y);
            ffma2(acc[3][2], kd3, vb.x); ffma2(acc[3][3], kd3, vb.y);
        }
    }

    float* p = g_part + ((long)(b * S1 + s)) * (DKC * DVC);
#pragma unroll
    for (int i = 0; i < 4; i++) {
        float* row = p + (k0 + i) * DVC + j0;
        *(ulonglong2*)(row)     = make_ulonglong2(acc[i][0], acc[i][1]);
        *(ulonglong2*)(row + 4) = make_ulonglong2(acc[i][2], acc[i][3]);
    }
}

// ============================================================================
// Phase 1b: reduce S1 partials -> g_ktv
// ============================================================================
__global__ __launch_bounds__(256) void reduce_kernel()
{
    const int o = blockIdx.x * 256 + threadIdx.x;   // 0..65535
    const int b = o >> 12;
    const int r = o & 4095;
    const float* p = g_part + (long)b * S1 * 4096 + r;
    float s = 0.f;
#pragma unroll
    for (int i = 0; i < S1; i++) s += p[i * 4096];
    g_ktv[o] = s;
}

// ============================================================================
// Phase 2: out[b,n,:] = q[b,:,n]^T @ ktv[b]
// Block: 256 threads over a 256-row n-chunk. Thread tile: 4 n x 16 j.
// Per k-step: 1 LDG.128 (q, coalesced) + 4 LDS.128 (ktv, broadcast) + 32 FFMA2.
// ============================================================================
__global__ __launch_bounds__(256) void phase2_kernel(
    const float* __restrict__ q, float* __restrict__ out)
{
    __shared__ float ktvs[DKC * DVC];

    const int b = blockIdx.y;
    const int t = threadIdx.x;

    const float4* src = (const float4*)(g_ktv + b * (DKC * DVC));
#pragma unroll
    for (int i = 0; i < 4; i++)
        ((float4*)ktvs)[t + i * 256] = src[t + i * 256];
    __syncthreads();

    const int ng = t & 63;          // 0..63
    const int jg = t >> 6;          // 0..3
    const int n0 = blockIdx.x * 256 + ng * 4;
    const int j0 = jg * 16;

    unsigned long long acc[4][8];
#pragma unroll
    for (int i = 0; i < 4; i++)
#pragma unroll
        for (int p = 0; p < 8; p++) acc[i][p] = 0ULL;

    const float* qp = q + (long)b * DKC * NSEQ + n0;

#pragma unroll 4
    for (int kk = 0; kk < DKC; kk++) {
        float4 q4 = *(const float4*)(qp + (long)kk * NSEQ);
        ulonglong2 p0 = *(const ulonglong2*)(ktvs + kk * 64 + j0);
        ulonglong2 p1 = *(const ulonglong2*)(ktvs + kk * 64 + j0 + 4);
        ulonglong2 p2 = *(const ulonglong2*)(ktvs + kk * 64 + j0 + 8);
        ulonglong2 p3 = *(const ulonglong2*)(ktvs + kk * 64 + j0 + 12);
        unsigned long long qd0 = pack2(q4.x);
        unsigned long long qd1 = pack2(q4.y);
        unsigned long long qd2 = pack2(q4.z);
        unsigned long long qd3 = pack2(q4.w);

        ffma2(acc[0][0], qd0, p0.x); ffma2(acc[0][1], qd0, p0.y);
        ffma2(acc[0][2], qd0, p1.x); ffma2(acc[0][3], qd0, p1.y);
        ffma2(acc[0][4], qd0, p2.x); ffma2(acc[0][5], qd0, p2.y);
        ffma2(acc[0][6], qd0, p3.x); ffma2(acc[0][7], qd0, p3.y);

        ffma2(acc[1][0], qd1, p0.x); ffma2(acc[1][1], qd1, p0.y);
        ffma2(acc[1][2], qd1, p1.x); ffma2(acc[1][3], qd1, p1.y);
        ffma2(acc[1][4], qd1, p2.x); ffma2(acc[1][5], qd1, p2.y);
        ffma2(acc[1][6], qd1, p3.x); ffma2(acc[1][7], qd1, p3.y);

        ffma2(acc[2][0], qd2, p0.x); ffma2(acc[2][1], qd2, p0.y);
        ffma2(acc[2][2], qd2, p1.x); ffma2(acc[2][3], qd2, p1.y);
        ffma2(acc[2][4], qd2, p2.x); ffma2(acc[2][5], qd2, p2.y);
        ffma2(acc[2][6], qd2, p3.x); ffma2(acc[2][7], qd2, p3.y);

        ffma2(acc[3][0], qd3, p0.x); ffma2(acc[3][1], qd3, p0.y);
        ffma2(acc[3][2], qd3, p1.x); ffma2(acc[3][3], qd3, p1.y);
        ffma2(acc[3][4], qd3, p2.x); ffma2(acc[3][5], qd3, p2.y);
        ffma2(acc[3][6], qd3, p3.x); ffma2(acc[3][7], qd3, p3.y);
    }

    float* op = out + ((long)b * NSEQ + n0) * DVC + j0;
#pragma unroll
    for (int i = 0; i < 4; i++) {
        float* row = op + (long)i * DVC;
        *(ulonglong2*)(row)      = make_ulonglong2(acc[i][0], acc[i][1]);
        *(ulonglong2*)(row + 4)  = make_ulonglong2(acc[i][2], acc[i][3]);
        *(ulonglong2*)(row + 8)  = make_ulonglong2(acc[i][4], acc[i][5]);
        *(ulonglong2*)(row + 12) = make_ulonglong2(acc[i][6], acc[i][7]);
    }
}

extern "C" void kernel_launch(void* const* d_in, const int* in_sizes, int n_in,
                              void* d_out, int out_size)
{
    const float* q = (const float*)d_in[0];
    const float* k = (const float*)d_in[1];
    const float* v = (const float*)d_in[2];
    float* out = (float*)d_out;

    phase1_kernel<<<dim3(S1, BATCH), 128>>>(k, v);
    reduce_kernel<<<(BATCH * DKC * DVC) / 256, 256>>>();
    phase2_kernel<<<dim3(NSEQ / 256, BATCH), 256>>>(q, out);
}

// round 5
// speedup vs baseline: 1.1817x; 1.1817x over previous
#include <cuda_runtime.h>
#include <cstdint>

// LinearAttention: B=16, DK=64, N=8192, DV=64, fp32.
//   ktv[b,k,j] = sum_n k[b,n,k] * v[b,n,j]
//   out[b,n,j] = sum_k q[b,k,n] * ktv[b,k,j]
// Inputs: q [B,DK,N], k [B,N,DK], v [B,N,DV]. Output [B,N,DV] fp32.

#define BATCH  16
#define DKC    64
#define NSEQ   8192
#define DVC    64
#define S1B    32                 // phase-1 blocks per batch
#define GROUPS 4                  // independent 64-thread output groups per block
#define SPLITS (S1B * GROUPS)     // 128 partials per batch
#define ROWS_PB (NSEQ / S1B)      // 256 rows per block
#define TROWS  32                 // rows per smem tile
#define NTILES (ROWS_PB / TROWS)  // 8

__device__ float g_part[BATCH * SPLITS * DKC * DVC];  // 32 MB partial ktv
__device__ float g_ktv [BATCH * DKC * DVC];

typedef unsigned long long ull;

// ---- packed f32x2 helpers (Blackwell FFMA2 via PTX) ----
__device__ __forceinline__ ull pack2(float x) {
    ull r;
    asm("mov.b64 %0, {%1, %1};" : "=l"(r) : "f"(x));
    return r;
}
__device__ __forceinline__ void ffma2(ull& d, ull a, ull b) {
    asm("fma.rn.f32x2 %0, %1, %2, %0;" : "+l"(d) : "l"(a), "l"(b));
}
__device__ __forceinline__ void cp16(uint32_t dst, const void* src) {
    asm volatile("cp.async.cg.shared.global [%0], [%1], 16;" :: "r"(dst), "l"(src));
}
__device__ __forceinline__ void cp_commit() {
    asm volatile("cp.async.commit_group;");
}
__device__ __forceinline__ void cp_wait0() {
    asm volatile("cp.async.wait_group 0;");
}

// ============================================================================
// Phase 1: partial ktv = k_chunk^T @ v_chunk.
// 256 threads = 4 groups of 64; group g accumulates rows [g*8, g*8+8) of each
// 32-row tile into its own 64x64 partial (8x8 per-thread tile, f32x2 accs).
// cp.async double-buffered tiles overlap gmem loads with FFMA2 compute.
// ============================================================================
__global__ __launch_bounds__(256, 2) void phase1_kernel(
    const float* __restrict__ kmat, const float* __restrict__ vmat)
{
    __shared__ float ks[2][TROWS * 64];
    __shared__ float vs[2][TROWS * 64];

    const int b   = blockIdx.y;
    const int blk = blockIdx.x;
    const int t   = threadIdx.x;
    const int g   = t >> 6;
    const int tg  = t & 63;
    const int k0  = (tg >> 3) * 8;
    const int j0  = (tg & 7) * 8;

    ull acc[8][4];
#pragma unroll
    for (int i = 0; i < 8; i++)
#pragma unroll
        for (int p = 0; p < 4; p++) acc[i][p] = 0ULL;

    const long base = ((long)b * NSEQ + (long)blk * ROWS_PB) * 64;
    const float4* kg4 = (const float4*)(kmat + base);
    const float4* vg4 = (const float4*)(vmat + base);

    const uint32_t ks0 = (uint32_t)__cvta_generic_to_shared(&ks[0][0]);
    const uint32_t vs0 = (uint32_t)__cvta_generic_to_shared(&vs[0][0]);
    const uint32_t BUFB = TROWS * 64 * 4;  // 8192 bytes per buffer

    // tile T (512 float4 each for k and v), 4 cp.async per thread
    auto load_tile = [&](int buf, int T) {
        const float4* kp = kg4 + T * 512;
        const float4* vp = vg4 + T * 512;
        uint32_t kb = ks0 + buf * BUFB;
        uint32_t vb = vs0 + buf * BUFB;
        cp16(kb + (uint32_t)t * 16,         kp + t);
        cp16(kb + (uint32_t)(t + 256) * 16, kp + t + 256);
        cp16(vb + (uint32_t)t * 16,         vp + t);
        cp16(vb + (uint32_t)(t + 256) * 16, vp + t + 256);
        cp_commit();
    };

    load_tile(0, 0);
    cp_wait0();
    __syncthreads();

    for (int T = 0; T < NTILES; T++) {
        const int cur = T & 1;
        if (T + 1 < NTILES) load_tile(cur ^ 1, T + 1);

        const float* kbuf = &ks[cur][0];
        const float* vbuf = &vs[cur][0];
#pragma unroll
        for (int n = 0; n < 8; n++) {
            const int row = g * 8 + n;
            float4 ka = *(const float4*)(kbuf + row * 64 + k0);
            float4 kb = *(const float4*)(kbuf + row * 64 + k0 + 4);
            ulonglong2 va = *(const ulonglong2*)(vbuf + row * 64 + j0);
            ulonglong2 vb2 = *(const ulonglong2*)(vbuf + row * 64 + j0 + 4);
            ull kd[8];
            kd[0] = pack2(ka.x); kd[1] = pack2(ka.y);
            kd[2] = pack2(ka.z); kd[3] = pack2(ka.w);
            kd[4] = pack2(kb.x); kd[5] = pack2(kb.y);
            kd[6] = pack2(kb.z); kd[7] = pack2(kb.w);
#pragma unroll
            for (int i = 0; i < 8; i++) {
                ffma2(acc[i][0], kd[i], va.x);
                ffma2(acc[i][1], kd[i], va.y);
                ffma2(acc[i][2], kd[i], vb2.x);
                ffma2(acc[i][3], kd[i], vb2.y);
            }
        }

        if (T + 1 < NTILES) {
            cp_wait0();
            __syncthreads();
        }
    }

    const int s = blk * GROUPS + g;
    float* p = g_part + ((long)(b * SPLITS + s)) * (DKC * DVC);
#pragma unroll
    for (int i = 0; i < 8; i++) {
        float* row = p + (k0 + i) * DVC + j0;
        *(ulonglong2*)(row)     = make_ulonglong2(acc[i][0], acc[i][1]);
        *(ulonglong2*)(row + 4) = make_ulonglong2(acc[i][2], acc[i][3]);
    }
}

// ============================================================================
// Phase 1b: fold SPLITS partials -> g_ktv  (coalesced, ~32MB read)
// ============================================================================
__global__ __launch_bounds__(256) void reduce_kernel()
{
    const int o = blockIdx.x * 256 + threadIdx.x;   // 0..65535
    const int b = o >> 12;
    const int r = o & 4095;
    const float* p = g_part + (long)b * SPLITS * 4096 + r;
    float s = 0.f;
#pragma unroll 8
    for (int i = 0; i < SPLITS; i++) s += p[i * 4096];
    g_ktv[o] = s;
}

// ============================================================================
// Phase 2: out[b,n,:] = q[b,:,n]^T @ ktv[b]
// 256 threads, thread tile 8n x 8j (jg = lane-contiguous -> coalesced stores,
// fully-broadcast ktv LDS). Manual double-prefetch of q.
// ============================================================================
__global__ __launch_bounds__(256, 2) void phase2_kernel(
    const float* __restrict__ q, float* __restrict__ out)
{
    __shared__ float ktvs[DKC * DVC];

    const int b = blockIdx.y;
    const int t = threadIdx.x;

    const float4* src = (const float4*)(g_ktv + b * (DKC * DVC));
#pragma unroll
    for (int i = 0; i < 4; i++)
        ((float4*)ktvs)[t + i * 256] = src[t + i * 256];
    __syncthreads();

    const int jg = t & 7;
    const int ng = t >> 3;              // 0..31
    const int n0 = blockIdx.x * 256 + ng * 8;
    const int j0 = jg * 8;

    ull acc[8][4];
#pragma unroll
    for (int i = 0; i < 8; i++)
#pragma unroll
        for (int p = 0; p < 4; p++) acc[i][p] = 0ULL;

    const float* qp = q + (long)b * DKC * NSEQ + n0;

    float4 qa = *(const float4*)(qp);
    float4 qb = *(const float4*)(qp + 4);

#pragma unroll 8
    for (int kk = 0; kk < DKC; kk++) {
        float4 ca = qa, cb = qb;
        if (kk < DKC - 1) {
            qa = *(const float4*)(qp + (long)(kk + 1) * NSEQ);
            qb = *(const float4*)(qp + (long)(kk + 1) * NSEQ + 4);
        }
        ulonglong2 p0 = *(const ulonglong2*)(ktvs + kk * 64 + j0);
        ulonglong2 p1 = *(const ulonglong2*)(ktvs + kk * 64 + j0 + 4);
        ull qd[8];
        qd[0] = pack2(ca.x); qd[1] = pack2(ca.y);
        qd[2] = pack2(ca.z); qd[3] = pack2(ca.w);
        qd[4] = pack2(cb.x); qd[5] = pack2(cb.y);
        qd[6] = pack2(cb.z); qd[7] = pack2(cb.w);
#pragma unroll
        for (int i = 0; i < 8; i++) {
            ffma2(acc[i][0], qd[i], p0.x);
            ffma2(acc[i][1], qd[i], p0.y);
            ffma2(acc[i][2], qd[i], p1.x);
            ffma2(acc[i][3], qd[i], p1.y);
        }
    }

    float* op = out + ((long)b * NSEQ + n0) * DVC + j0;
#pragma unroll
    for (int i = 0; i < 8; i++) {
        float* row = op + (long)i * DVC;
        *(ulonglong2*)(row)     = make_ulonglong2(acc[i][0], acc[i][1]);
        *(ulonglong2*)(row + 4) = make_ulonglong2(acc[i][2], acc[i][3]);
    }
}

extern "C" void kernel_launch(void* const* d_in, const int* in_sizes, int n_in,
                              void* d_out, int out_size)
{
    const float* q = (const float*)d_in[0];
    const float* k = (const float*)d_in[1];
    const float* v = (const float*)d_in[2];
    float* out = (float*)d_out;

    phase1_kernel<<<dim3(S1B, BATCH), 256>>>(k, v);
    reduce_kernel<<<(BATCH * DKC * DVC) / 256, 256>>>();
    phase2_kernel<<<dim3(NSEQ / 256, BATCH), 256>>>(q, out);
}

// round 7
// speedup vs baseline: 1.5387x; 1.3021x over previous
#include <cuda_runtime.h>
#include <cstdint>

// LinearAttention: B=16, DK=64, N=8192, DV=64, fp32.
//   ktv[b,k,j] = sum_n k[b,n,k] * v[b,n,j]
//   out[b,n,j] = sum_k q[b,k,n] * ktv[b,k,j]
// Inputs: q [B,DK,N], k [B,N,DK], v [B,N,DV]. Output [B,N,DV] fp32.
//
// Both GEMMs run on tensor cores via mma.sync.m16n8k8.tf32 (3-pass hi/lo
// split for fp32-grade accuracy). tcgen05 is unusable: harness compiles
// with virtual arch compute_103 (no 'a'), which gates out accel features.

#define BATCH  16
#define DKC    64
#define NSEQ   8192
#define DVC    64
#define S1B    32                 // phase-1 blocks per batch
#define ROWS_PB (NSEQ / S1B)      // 256 n-rows per phase-1 block
#define TROWS  32                 // rows per smem tile
#define NTILES (ROWS_PB / TROWS)  // 8
#define P1_STRIDE 72              // padded smem row stride (floats), bank-safe
#define P2_QSTRIDE 136
#define P2_KSTRIDE 72

__device__ float g_part[BATCH * S1B * DKC * DVC];  // 8 MB partial ktv
__device__ float g_ktv [BATCH * DKC * DVC];

// ---------------- helpers ----------------
__device__ __forceinline__ void cp16(uint32_t dst, const void* src) {
    asm volatile("cp.async.cg.shared.global [%0], [%1], 16;" :: "r"(dst), "l"(src));
}
__device__ __forceinline__ void cp_commit() { asm volatile("cp.async.commit_group;"); }
__device__ __forceinline__ void cp_wait0()  { asm volatile("cp.async.wait_group 0;"); }
__device__ __forceinline__ uint32_t smem_u32(const void* p) {
    uint32_t a;
    asm("{ .reg .u64 t; cvta.to.shared.u64 t, %1; cvt.u32.u64 %0, t; }" : "=r"(a) : "l"(p));
    return a;
}
__device__ __forceinline__ uint32_t tf32_of(float x) {
    uint32_t r; asm("cvt.rna.tf32.f32 %0, %1;" : "=r"(r) : "f"(x)); return r;
}
// hi/lo split: x ~= hi + lo, both representable in tf32
__device__ __forceinline__ void tf32_split(float x, uint32_t& hi, uint32_t& lo) {
    hi = tf32_of(x);
    lo = tf32_of(x - __uint_as_float(hi));
}
__device__ __forceinline__ void mma_tf32(float* d,
                                         uint32_t a0, uint32_t a1, uint32_t a2, uint32_t a3,
                                         uint32_t b0, uint32_t b1) {
    asm volatile("mma.sync.aligned.m16n8k8.row.col.f32.tf32.tf32.f32 "
                 "{%0,%1,%2,%3}, {%4,%5,%6,%7}, {%8,%9}, {%0,%1,%2,%3};"
                 : "+f"(d[0]), "+f"(d[1]), "+f"(d[2]), "+f"(d[3])
                 : "r"(a0), "r"(a1), "r"(a2), "r"(a3), "r"(b0), "r"(b1));
}

// ============================================================================
// Phase 1: partial ktv = k_chunk^T @ v_chunk via tensor cores.
// Block 128 threads (4 warps). Warp w owns dk rows [16w,16w+16) x all 64 j.
// mma mapping: m=dk, contraction k=n (8 per step), n'=j.
//   A[m=dk, k=n] = k_tile[n][dk]   (natural layout, single-element frags)
//   B[k=n, n'=j] = v_tile[n][j]    (natural layout)
// cp.async double-buffered 32-row tiles.
// ============================================================================
__global__ __launch_bounds__(128, 3) void phase1_kernel(
    const float* __restrict__ kmat, const float* __restrict__ vmat)
{
    __shared__ float ks[2][TROWS * P1_STRIDE];
    __shared__ float vs[2][TROWS * P1_STRIDE];

    const int b    = blockIdx.y;
    const int blk  = blockIdx.x;
    const int t    = threadIdx.x;
    const int w    = t >> 5;
    const int lane = t & 31;
    const int g    = lane >> 2;   // groupID 0..7
    const int tg   = lane & 3;    // threadID_in_group 0..3

    float acc[8][4];
#pragma unroll
    for (int jt = 0; jt < 8; jt++)
#pragma unroll
        for (int p = 0; p < 4; p++) acc[jt][p] = 0.f;

    const long base = ((long)b * NSEQ + (long)blk * ROWS_PB) * 64;
    const float4* kg4 = (const float4*)(kmat + base);
    const float4* vg4 = (const float4*)(vmat + base);

    const uint32_t ks0 = smem_u32(&ks[0][0]);
    const uint32_t vs0 = smem_u32(&vs[0][0]);
    const uint32_t BUFB = TROWS * P1_STRIDE * 4;

    // one 32x64 tile = 512 float4 per matrix; 4 cp.async per thread per matrix
    auto load_tile = [&](int buf, int T) {
        const float4* kp = kg4 + T * 512;
        const float4* vp = vg4 + T * 512;
        uint32_t kb = ks0 + buf * BUFB;
        uint32_t vb = vs0 + buf * BUFB;
#pragma unroll
        for (int i = 0; i < 4; i++) {
            int idx = t + i * 128;            // 0..511
            int r = idx >> 4, c = idx & 15;
            uint32_t off = (uint32_t)(r * P1_STRIDE + c * 4) * 4;
            cp16(kb + off, kp + idx);
            cp16(vb + off, vp + idx);
        }
        cp_commit();
    };

    load_tile(0, 0);
    cp_wait0();
    __syncthreads();

    const int kd0 = 16 * w;

    for (int T = 0; T < NTILES; T++) {
        const int cur = T & 1;
        if (T + 1 < NTILES) load_tile(cur ^ 1, T + 1);

        const float* kbuf = &ks[cur][0];
        const float* vbuf = &vs[cur][0];

#pragma unroll
        for (int nb = 0; nb < TROWS; nb += 8) {
            const int r0 = nb + tg;
            const int r1 = nb + tg + 4;
            // A frags (hi/lo): A[m=dk, k=n] = k_tile[n][dk]
            uint32_t ah[4], al[4];
            tf32_split(kbuf[r0 * P1_STRIDE + kd0 + g],     ah[0], al[0]);
            tf32_split(kbuf[r0 * P1_STRIDE + kd0 + g + 8], ah[1], al[1]);
            tf32_split(kbuf[r1 * P1_STRIDE + kd0 + g],     ah[2], al[2]);
            tf32_split(kbuf[r1 * P1_STRIDE + kd0 + g + 8], ah[3], al[3]);
#pragma unroll
            for (int jt = 0; jt < 8; jt++) {
                uint32_t bh0, bl0, bh1, bl1;
                tf32_split(vbuf[r0 * P1_STRIDE + jt * 8 + g], bh0, bl0);
                tf32_split(vbuf[r1 * P1_STRIDE + jt * 8 + g], bh1, bl1);
                mma_tf32(acc[jt], ah[0], ah[1], ah[2], ah[3], bh0, bh1);
                mma_tf32(acc[jt], ah[0], ah[1], ah[2], ah[3], bl0, bl1);
                mma_tf32(acc[jt], al[0], al[1], al[2], al[3], bh0, bh1);
            }
        }

        if (T + 1 < NTILES) { cp_wait0(); __syncthreads(); }
    }

    // epilogue: C tile (m16 x n8): c0,c1 at (dk=kd0+g, j=jt*8+2tg), c2,c3 at dk+8
    float* p = g_part + ((long)(b * S1B + blk)) * (DKC * DVC);
#pragma unroll
    for (int jt = 0; jt < 8; jt++) {
        const int j = jt * 8 + 2 * tg;
        *(float2*)(p + (kd0 + g) * DVC + j)     = make_float2(acc[jt][0], acc[jt][1]);
        *(float2*)(p + (kd0 + g + 8) * DVC + j) = make_float2(acc[jt][2], acc[jt][3]);
    }
}

// ============================================================================
// Phase 1b: fold S1B partials -> g_ktv (8MB read, coalesced)
// ============================================================================
__global__ __launch_bounds__(256) void reduce_kernel()
{
    const int o = blockIdx.x * 256 + threadIdx.x;   // 0..65535
    const int b = o >> 12;
    const int r = o & 4095;
    const float* p = g_part + (long)b * S1B * 4096 + r;
    float s = 0.f;
#pragma unroll 8
    for (int i = 0; i < S1B; i++) s += p[i * 4096];
    g_ktv[o] = s;
}

// ============================================================================
// Phase 2: out = q^T @ ktv via tensor cores.
// Block 128 threads (4 warps), 128-row n-tile. Warp w owns n rows [32w,32w+32)
// (2 m-tiles) x 64 j. mma mapping: m=n, contraction k=dk, n'=j.
//   A[m=n, k=dk] = q_tile[dk][n]   (natural: q is [DK,N] channel-first)
//   B[k=dk, n'=j] = ktv[dk][j]     (natural layout)
// ============================================================================
__global__ __launch_bounds__(128, 2) void phase2_kernel(
    const float* __restrict__ q, float* __restrict__ out)
{
    __shared__ float qs[DKC * P2_QSTRIDE];   // 64 x 136 floats = 34 KB
    __shared__ float kt[DKC * P2_KSTRIDE];   // 64 x 72 floats  = 18 KB

    const int b    = blockIdx.y;
    const int n0   = blockIdx.x * 128;
    const int t    = threadIdx.x;
    const int w    = t >> 5;
    const int lane = t & 31;
    const int g    = lane >> 2;
    const int tg   = lane & 3;

    // stage ktv (fp32), 4096 elems
    {
        const float* src = g_ktv + b * (DKC * DVC);
#pragma unroll
        for (int i = 0; i < 32; i++) {
            int idx = t + i * 128;
            kt[(idx >> 6) * P2_KSTRIDE + (idx & 63)] = src[idx];
        }
    }
    // stage q tile: row dk, 128 n-cols (coalesced along n)
    {
        const float* qp = q + (long)b * DKC * NSEQ + n0 + t;
#pragma unroll 8
        for (int kd = 0; kd < DKC; kd++)
            qs[kd * P2_QSTRIDE + t] = qp[(long)kd * NSEQ];
    }
    __syncthreads();

    float acc[2][8][4];
#pragma unroll
    for (int mt = 0; mt < 2; mt++)
#pragma unroll
        for (int jt = 0; jt < 8; jt++)
#pragma unroll
            for (int p = 0; p < 4; p++) acc[mt][jt][p] = 0.f;

#pragma unroll
    for (int ksp = 0; ksp < 8; ksp++) {
        const int r0 = ksp * 8 + tg;
        const int r1 = ksp * 8 + tg + 4;

        // B frags (shared across both m-tiles)
        uint32_t bh[8][2], bl[8][2];
#pragma unroll
        for (int jt = 0; jt < 8; jt++) {
            tf32_split(kt[r0 * P2_KSTRIDE + jt * 8 + g], bh[jt][0], bl[jt][0]);
            tf32_split(kt[r1 * P2_KSTRIDE + jt * 8 + g], bh[jt][1], bl[jt][1]);
        }

#pragma unroll
        for (int mt = 0; mt < 2; mt++) {
            const int nb = 32 * w + 16 * mt;
            uint32_t ah[4], al[4];
            tf32_split(qs[r0 * P2_QSTRIDE + nb + g],     ah[0], al[0]);
            tf32_split(qs[r0 * P2_QSTRIDE + nb + g + 8], ah[1], al[1]);
            tf32_split(qs[r1 * P2_QSTRIDE + nb + g],     ah[2], al[2]);
            tf32_split(qs[r1 * P2_QSTRIDE + nb + g + 8], ah[3], al[3]);
#pragma unroll
            for (int jt = 0; jt < 8; jt++) {
                mma_tf32(acc[mt][jt], ah[0], ah[1], ah[2], ah[3], bh[jt][0], bh[jt][1]);
                mma_tf32(acc[mt][jt], ah[0], ah[1], ah[2], ah[3], bl[jt][0], bl[jt][1]);
                mma_tf32(acc[mt][jt], al[0], al[1], al[2], al[3], bh[jt][0], bh[jt][1]);
            }
        }
    }

    // epilogue: rows n = n0 + 32w + 16mt + g (+8), cols j = jt*8 + 2tg
#pragma unroll
    for (int mt = 0; mt < 2; mt++) {
        const int nrow = n0 + 32 * w + 16 * mt + g;
        float* o0 = out + ((long)b * NSEQ + nrow) * DVC;
        float* o1 = out + ((long)b * NSEQ + nrow + 8) * DVC;
#pragma unroll
        for (int jt = 0; jt < 8; jt++) {
            const int j = jt * 8 + 2 * tg;
            *(float2*)(o0 + j) = make_float2(acc[mt][jt][0], acc[mt][jt][1]);
            *(float2*)(o1 + j) = make_float2(acc[mt][jt][2], acc[mt][jt][3]);
        }
    }
}

extern "C" void kernel_launch(void* const* d_in, const int* in_sizes, int n_in,
                              void* d_out, int out_size)
{
    const float* q = (const float*)d_in[0];
    const float* k = (const float*)d_in[1];
    const float* v = (const float*)d_in[2];
    float* out = (float*)d_out;

    phase1_kernel<<<dim3(S1B, BATCH), 128>>>(k, v);
    reduce_kernel<<<(BATCH * DKC * DVC) / 256, 256>>>();
    phase2_kernel<<<dim3(NSEQ / 128, BATCH), 128>>>(q, out);
}